// round 9
// baseline (speedup 1.0000x reference)
#include <cuda_runtime.h>
#include <math_constants.h>

// Cumulative max along H for x[B=32, C=1, H=1024, W=2048] fp32.
// Single streaming pass: 256 MB read + 256 MB write (the traffic floor).
//
// R7: float4 columns + rolling ring-buffer pipeline (depth U=20).
// Per-byte instruction cost halves vs float2 (LDG.128/STG.128), which
// R6 showed is the binding overhead near the HBM ceiling (scalar was
// WORSE despite 2x warps). Each step refills buf[i] with the row U
// ahead BEFORE consuming, so 320 B/thread (~5.2 MB chip-wide) stays
// continuously in flight with no drain windows (the defect that sank
// the R2 float4 kernel). Streaming cache hints: no byte is reused.

static constexpr int B = 32;
static constexpr int H = 1024;
static constexpr int W = 2048;
static constexpr int W4 = W / 4;             // 512 float4 per row
static constexpr int NCOLS = B * W4;         // 16384 threads
static constexpr int U = 20;                 // pipeline depth (float4 loads)
static constexpr int NFULL = (H / U) - 1;    // full steady-state chunks
static constexpr int TAIL = H - NFULL * U;   // rows left after steady state

__global__ void __launch_bounds__(32)
cummax_h_kernel(const float4* __restrict__ x, float4* __restrict__ out) {
    int c = blockIdx.x * blockDim.x + threadIdx.x;   // 0 .. NCOLS-1

    int b  = c >> 9;           // c / 512
    int w4 = c & (W4 - 1);     // c % 512

    const float4* __restrict__ p = x   + (size_t)b * H * W4 + w4;
    float4*       __restrict__ q = out + (size_t)b * H * W4 + w4;

    float4 m = make_float4(-CUDART_INF_F, -CUDART_INF_F,
                           -CUDART_INF_F, -CUDART_INF_F);

    float4 buf[U];

    // Prologue: fill the pipeline with rows 0..U-1.
    #pragma unroll
    for (int i = 0; i < U; i++)
        buf[i] = __ldcs(p + (size_t)i * W4);

    // Steady state: consume row hCur+i while refilling with row hCur+i+U.
    // The refill load is independent of the fmax chain and issues first,
    // keeping U LDG.128 in flight per thread continuously.
    for (int cc = 0; cc < NFULL; cc++) {
        int hCur = cc * U;
        int hNxt = hCur + U;
        #pragma unroll
        for (int i = 0; i < U; i++) {
            float4 v = buf[i];
            buf[i] = __ldcs(p + (size_t)(hNxt + i) * W4);
            m.x = fmaxf(m.x, v.x);
            m.y = fmaxf(m.y, v.y);
            m.z = fmaxf(m.z, v.z);
            m.w = fmaxf(m.w, v.w);
            __stcs(q + (size_t)(hCur + i) * W4, m);
        }
    }

    // Epilogue: drain the buffer (rows NFULL*U .. NFULL*U+U-1), then
    // finish any remaining rows directly (TAIL - U of them; here
    // H=1024, U=20 -> NFULL=50, TAIL=24: 20 from buffer + 4 direct).
    {
        int hCur = NFULL * U;
        #pragma unroll
        for (int i = 0; i < U; i++) {
            m.x = fmaxf(m.x, buf[i].x);
            m.y = fmaxf(m.y, buf[i].y);
            m.z = fmaxf(m.z, buf[i].z);
            m.w = fmaxf(m.w, buf[i].w);
            __stcs(q + (size_t)(hCur + i) * W4, m);
        }
        #pragma unroll
        for (int i = U; i < TAIL; i++) {
            float4 v = __ldcs(p + (size_t)(hCur + i) * W4);
            m.x = fmaxf(m.x, v.x);
            m.y = fmaxf(m.y, v.y);
            m.z = fmaxf(m.z, v.z);
            m.w = fmaxf(m.w, v.w);
            __stcs(q + (size_t)(hCur + i) * W4, m);
        }
    }
}

extern "C" void kernel_launch(void* const* d_in, const int* in_sizes, int n_in,
                              void* d_out, int out_size) {
    const float4* x   = (const float4*)d_in[0];
    float4*       out = (float4*)d_out;

    // 512 blocks x 32 threads = 16384 threads, one per float4 column.
    cummax_h_kernel<<<NCOLS / 32, 32>>>(x, out);
}

// round 10
// speedup vs baseline: 1.1282x; 1.1282x over previous
#include <cuda_runtime.h>
#include <math_constants.h>

// Cumulative max along H for x[B=32, C=1, H=1024, W=2048] fp32.
// Single streaming pass: 256 MB read + 256 MB write (the traffic floor).
//
// R8 = R5 (the measured optimum: float2 columns, 6.9 warps/SM, U=32
// rolling ring-buffer pipeline) + paired load issue: the two refill
// LDG.64s of a step issue back-to-back at the LSU accept floor before
// the two dependent fmax->STG consume sequences, raising load-issue
// density per scheduler window. R6 (scalar, 2x warps) and R7 (float4,
// 0.5x warps) both measured worse -> float2 @ 32768 threads is the
// peak of the TLP/instr-overhead tradeoff. Streaming cache hints:
// no byte is reused.

static constexpr int B = 32;
static constexpr int H = 1024;
static constexpr int W = 2048;
static constexpr int W2 = W / 2;            // 1024 float2 per row
static constexpr int NCOLS = B * W2;        // 32768 threads
static constexpr int U = 32;                // pipeline depth (float2 loads)
static constexpr int NCHUNK = H / U;        // 32 chunks

__global__ void __launch_bounds__(32)
cummax_h_kernel(const float2* __restrict__ x, float2* __restrict__ out) {
    int c = blockIdx.x * blockDim.x + threadIdx.x;   // 0 .. NCOLS-1

    int b  = c >> 10;          // c / 1024
    int w2 = c & (W2 - 1);     // c % 1024

    const float2* __restrict__ p = x   + (size_t)b * H * W2 + w2;
    float2*       __restrict__ q = out + (size_t)b * H * W2 + w2;

    float2 m = make_float2(-CUDART_INF_F, -CUDART_INF_F);

    float2 buf[U];

    // Prologue: fill the pipeline with rows 0..U-1.
    #pragma unroll
    for (int i = 0; i < U; i++)
        buf[i] = __ldcs(p + (size_t)i * W2);

    // Steady state: per 2-row step, issue BOTH refill loads (independent,
    // back-to-back LDG at the LSU 4-cyc accept floor), then run the two
    // dependent fmax->store sequences. U loads stay in flight always.
    for (int cc = 0; cc < NCHUNK - 1; cc++) {
        int hCur = cc * U;
        int hNxt = hCur + U;
        #pragma unroll
        for (int i = 0; i < U; i += 2) {
            float2 v0 = buf[i];
            float2 v1 = buf[i + 1];
            buf[i]     = __ldcs(p + (size_t)(hNxt + i) * W2);
            buf[i + 1] = __ldcs(p + (size_t)(hNxt + i + 1) * W2);
            m.x = fmaxf(m.x, v0.x);
            m.y = fmaxf(m.y, v0.y);
            __stcs(q + (size_t)(hCur + i) * W2, m);
            m.x = fmaxf(m.x, v1.x);
            m.y = fmaxf(m.y, v1.y);
            __stcs(q + (size_t)(hCur + i + 1) * W2, m);
        }
    }

    // Epilogue: drain the last chunk (rows H-U .. H-1).
    {
        int hCur = (NCHUNK - 1) * U;
        #pragma unroll
        for (int i = 0; i < U; i++) {
            m.x = fmaxf(m.x, buf[i].x);
            m.y = fmaxf(m.y, buf[i].y);
            __stcs(q + (size_t)(hCur + i) * W2, m);
        }
    }
}

extern "C" void kernel_launch(void* const* d_in, const int* in_sizes, int n_in,
                              void* d_out, int out_size) {
    const float2* x   = (const float2*)d_in[0];
    float2*       out = (float2*)d_out;

    // 1024 blocks x 32 threads = 32768 threads, one per float2 column.
    cummax_h_kernel<<<NCOLS / 32, 32>>>(x, out);
}